// round 8
// baseline (speedup 1.0000x reference)
#include <cuda_runtime.h>
#include <cuda_bf16.h>
#include <cstdint>

// ---------------------------------------------------------------------------
// MAUCHLoss fused single-kernel, warp-specialized TMA pipeline (12 stages).
//
//   sig   = sigmoid(x)
//   cel_e = l*sig - softplus(sig)   (== l*log(s2) + (1-l)*log(1-s2), s2=sig(sig))
//   per col c: Ssig[c], Slsig[c], Sl[c]
//   penalty[c] = 1 - Slsig/npos + (Ssig-Slsig)/(B-npos)
//   out[0] = cel + 0.1*(sum(penalty)/15);  out[1] = 0.1*penalty[14]
// softplus(u), u in (0,1): ln2 + u/2 + w*(1/8 - w/192 + w^2/2880), w=u^2
//
// Structure: 152 persistent CTAs (1/SM), 544 threads = 512 consumers +
// 1 producer warp. Producer drives a 12-stage ring of cp.async.bulk pairs
// (7.68 KB per array per stage). Consumers: thread t<256 -> row t cols 0..7,
// thread t>=256 -> row t-256 cols 8..14 (compile-time columns, warp-uniform).
// ---------------------------------------------------------------------------

#define NBLK        152
#define NCON        512             // consumer threads
#define NTHR        544             // + 1 producer warp
#define NSTG        12
#define TILE_FLOATS 1920            // 128 rows... (256 rows x 15 cols? -> 256*15/2 per half) = 128*15? NO: 1920 = 128*15? 128*15=1920 yes -> rows 0..127?? see below
#define TILE_ROWS   128             // 128 rows x 15 cols = 1920 floats
#define TILE_BYTES  7680            // per array
#define STAGE_BYTES 15360           // out + lab
#define NACC        46              // 15 Ssig + 15 Slsig + 15 Sl + 1 Swp
#define SMEM_DYN    (256 + NSTG * STAGE_BYTES)   // 184576 bytes

// NOTE on consumer mapping with TILE_ROWS=128 and 512 consumers:
//   threads 0..127   : row t,       cols 0..7   (8 elems)
//   threads 128..255 : row t-128,   cols 8..14  (7 elems)
//   threads 256..383 : row t-256 +? -- instead each PAIR of half-warps would
// To keep it simple and warp-uniform we use 256 rows per tile after all:
#undef TILE_FLOATS
#undef TILE_ROWS
#undef TILE_BYTES
#undef STAGE_BYTES
#undef SMEM_DYN
#define TILE_ROWS   256
#define TILE_FLOATS 3840            // 256 rows x 15 cols
#define TILE_BYTES  15360           // per array
#define STAGE_BYTES 30720
#define NSTG2       6               // 6 stages x 30 KB = 184 KB
#define SMEM_DYN    (256 + NSTG2 * STAGE_BYTES)  // 184576

__device__ float        g_scratch[NACC * NBLK];
__device__ unsigned int g_count;    // zero-init; reset by last block

__device__ __forceinline__ float fast_ex2(float a) {
    float r; asm("ex2.approx.ftz.f32 %0, %1;" : "=f"(r) : "f"(a)); return r;
}
__device__ __forceinline__ float fast_rcp(float a) {
    float r; asm("rcp.approx.ftz.f32 %0, %1;" : "=f"(r) : "f"(a)); return r;
}
__device__ __forceinline__ uint32_t smem_u32(const void* p) {
    uint32_t a;
    asm("{ .reg .u64 t; cvta.to.shared.u64 t, %1; cvt.u32.u64 %0, t; }"
        : "=r"(a) : "l"(p));
    return a;
}
__device__ __forceinline__ void mbar_init(uint32_t mbar, uint32_t cnt) {
    asm volatile("mbarrier.init.shared.b64 [%0], %1;" :: "r"(mbar), "r"(cnt) : "memory");
}
__device__ __forceinline__ void mbar_expect_tx(uint32_t mbar, uint32_t bytes) {
    asm volatile("mbarrier.arrive.expect_tx.shared.b64 _, [%0], %1;"
                 :: "r"(mbar), "r"(bytes) : "memory");
}
__device__ __forceinline__ void mbar_arrive(uint32_t mbar) {
    asm volatile("mbarrier.arrive.release.cta.shared::cta.b64 _, [%0];"
                 :: "r"(mbar) : "memory");
}
__device__ __forceinline__ void mbar_wait(uint32_t mbar, uint32_t parity) {
    asm volatile(
        "{\n\t"
        ".reg .pred P;\n\t"
        "WAIT_LOOP_%=:\n\t"
        "mbarrier.try_wait.parity.acquire.cta.shared::cta.b64 P, [%0], %1, 0x989680;\n\t"
        "@P bra.uni WAIT_DONE_%=;\n\t"
        "bra.uni WAIT_LOOP_%=;\n\t"
        "WAIT_DONE_%=:\n\t"
        "}"
        :: "r"(mbar), "r"(parity) : "memory");
}
__device__ __forceinline__ void bulk_g2s(uint32_t dst, const void* src,
                                         uint32_t bytes, uint32_t mbar) {
    asm volatile(
        "cp.async.bulk.shared::cluster.global.mbarrier::complete_tx::bytes "
        "[%0], [%1], %2, [%3];"
        :: "r"(dst), "l"(src), "r"(bytes), "r"(mbar) : "memory");
}

__global__ __launch_bounds__(NTHR)
void mauc_tma(const float* __restrict__ outp, const float* __restrict__ labp,
              float* __restrict__ out, int n)
{
    extern __shared__ char dsm[];
    const int tid = threadIdx.x;
    const int b   = blockIdx.x;

    const uint32_t smb = smem_u32(dsm);
    auto full_bar  = [&](int s) { return smb + (uint32_t)(s * 16); };
    auto empty_bar = [&](int s) { return smb + (uint32_t)(s * 16 + 8); };
    auto stage_out = [&](int s) { return dsm + 256 + (size_t)s * STAGE_BYTES; };
    auto stage_lab = [&](int s) { return dsm + 256 + (size_t)s * STAGE_BYTES + TILE_BYTES; };

    const int ntiles  = n / TILE_FLOATS;                       // 8192
    const int mytiles = (b < ntiles) ? (ntiles - b + NBLK - 1) / NBLK : 0;

    if (tid == 0) {
        for (int s = 0; s < NSTG2; s++) {
            mbar_init(full_bar(s), 1);
            mbar_init(empty_bar(s), NCON);
        }
    }
    __syncthreads();

    const float NLOG2E = -1.4426950408889634f;

    // per-thread accumulators (cols are compile-time-offset within the slot set)
    float a_s[8], a_ls[8], a_lb[8];
#pragma unroll
    for (int k = 0; k < 8; k++) { a_s[k] = 0.f; a_ls[k] = 0.f; a_lb[k] = 0.f; }
    float swp = 0.f;

    if (tid >= NCON) {
        // -------- producer warp (lane 0 issues) --------
        if ((tid & 31) == 0) {
            for (int j = 0; j < mytiles; j++) {
                const int s = j % NSTG2;
                if (j >= NSTG2)
                    mbar_wait(empty_bar(s), (uint32_t)(((j - NSTG2) / NSTG2) & 1));
                const size_t g = (size_t)(b + (size_t)j * NBLK) * TILE_FLOATS;
                mbar_expect_tx(full_bar(s), STAGE_BYTES);
                bulk_g2s(smem_u32(stage_out(s)), outp + g, TILE_BYTES, full_bar(s));
                bulk_g2s(smem_u32(stage_lab(s)), labp + g, TILE_BYTES, full_bar(s));
            }
        }
    } else {
        // -------- consumers --------
        const int  half = (tid >= 256) ? 1 : 0;      // warp-uniform (8 warps each)
        const int  row  = tid & 255;
        const int  boff = row * 15 + half * 8;       // word offset within tile
        const int  cnt  = half ? 7 : 8;

        for (int i = 0; i < mytiles; i++) {
            const int      s  = i % NSTG2;
            const uint32_t ph = (uint32_t)((i / NSTG2) & 1);
            mbar_wait(full_bar(s), ph);

            const float* ro = (const float*)stage_out(s) + boff;
            const float* rl = (const float*)stage_lab(s) + boff;

            if (half == 0) {
#pragma unroll
                for (int k = 0; k < 8; k++) {
                    float x  = ro[k];
                    float lb = rl[k];
                    float t   = fast_ex2(NLOG2E * x);
                    float sig = fast_rcp(1.0f + t);
                    float w   = sig * sig;
                    float p   = fmaf(fmaf(3.4722222e-4f, w, -5.2083333e-3f), w, 0.125f);
                    a_s[k]  += sig;
                    a_ls[k]  = fmaf(lb, sig, a_ls[k]);
                    a_lb[k] += lb;
                    swp      = fmaf(w, p, swp);
                }
            } else {
#pragma unroll
                for (int k = 0; k < 7; k++) {
                    float x  = ro[k];
                    float lb = rl[k];
                    float t   = fast_ex2(NLOG2E * x);
                    float sig = fast_rcp(1.0f + t);
                    float w   = sig * sig;
                    float p   = fmaf(fmaf(3.4722222e-4f, w, -5.2083333e-3f), w, 0.125f);
                    a_s[k]  += sig;
                    a_ls[k]  = fmaf(lb, sig, a_ls[k]);
                    a_lb[k] += lb;
                    swp      = fmaf(w, p, swp);
                }
            }
            mbar_arrive(empty_bar(s));
        }
        (void)cnt;
    }

    __syncthreads();   // pipeline fully drained; smem ring reusable

    // ---- stage per-thread sums into (reused) dynamic smem ----
    float* stg = (float*)dsm;     // [3][512][8] = 48 KB
    if (tid < NCON) {
#pragma unroll
        for (int k = 0; k < 8; k++) {
            stg[(0 * NCON + tid) * 8 + k] = a_s[k];
            stg[(1 * NCON + tid) * 8 + k] = a_ls[k];
            stg[(2 * NCON + tid) * 8 + k] = a_lb[k];
        }
    }

    // swp reduction across all 17 warps
    __shared__ float swarp[NTHR / 32];
    __shared__ float tot[NACC];
    __shared__ bool  is_last;
    const unsigned FULL = 0xFFFFFFFFu;
    const int wid  = tid >> 5;
    const int lane = tid & 31;
    {
        float sv = swp;
        sv += __shfl_down_sync(FULL, sv, 16);
        sv += __shfl_down_sync(FULL, sv, 8);
        sv += __shfl_down_sync(FULL, sv, 4);
        sv += __shfl_down_sync(FULL, sv, 2);
        sv += __shfl_down_sync(FULL, sv, 1);
        if (lane == 0) swarp[wid] = sv;
    }
    __syncthreads();

    if (tid < 45) {
        const int stat = tid / 15;
        const int col  = tid % 15;
        float s = 0.0f;
        if (col < 8) {
            for (int t = 0; t < 256; t++) s += stg[(stat * NCON + t) * 8 + col];
        } else {
            for (int t = 256; t < 512; t++) s += stg[(stat * NCON + t) * 8 + (col - 8)];
        }
        g_scratch[(stat * 15 + col) * NBLK + b] = s;
    } else if (tid == 64) {
        float s = 0.0f;
#pragma unroll
        for (int w = 0; w < NTHR / 32; w++) s += swarp[w];
        g_scratch[45 * NBLK + b] = s;
    }

    // ---- last-block-done: final reduction + scalar epilogue ----
    __threadfence();
    __syncthreads();
    if (tid == 0) {
        unsigned prev = atomicAdd(&g_count, 1u);
        is_last = (prev == gridDim.x - 1);
    }
    __syncthreads();
    if (!is_last) return;
    __threadfence();   // acquire: all g_scratch writes visible

    for (int v = wid; v < NACC; v += NTHR / 32) {
        float s = 0.0f;
        for (int bb = lane; bb < NBLK; bb += 32) s += g_scratch[v * NBLK + bb];
        s += __shfl_down_sync(FULL, s, 16);
        s += __shfl_down_sync(FULL, s, 8);
        s += __shfl_down_sync(FULL, s, 4);
        s += __shfl_down_sync(FULL, s, 2);
        s += __shfl_down_sync(FULL, s, 1);
        if (lane == 0) tot[v] = s;
    }
    __syncthreads();

    if (tid == 0) {
        double ssig[15], slsig[15], slbl[15];
        double sswp = (double)tot[45];
        for (int c = 0; c < 15; c++) {
            ssig[c]  = (double)tot[c];
            slsig[c] = (double)tot[15 + c];
            slbl[c]  = (double)tot[30 + c];
        }
        // remainder elements not covered by whole tiles (0 for this shape)
        for (int idx = ntiles * TILE_FLOATS; idx < n; idx++) {
            int   col = idx % 15;
            float x   = outp[idx];
            float lb  = labp[idx];
            float t   = fast_ex2(NLOG2E * x);
            float sig = fast_rcp(1.0f + t);
            float w   = sig * sig;
            float p   = fmaf(fmaf(3.4722222e-4f, w, -5.2083333e-3f), w, 0.125f);
            ssig[col]  += sig;
            slsig[col] += lb * sig;
            slbl[col]  += lb;
            sswp       += w * p;
        }

        const double LN2 = 0.6931471805599453;
        double N  = (double)n;
        double Bf = N / 15.0;

        double sum_sig_all = 0.0, sum_lsig_all = 0.0;
        double sum_term = 0.0, pen14 = 0.0;
        for (int c = 0; c < 15; c++) {
            sum_sig_all  += ssig[c];
            sum_lsig_all += slsig[c];
            double np = slbl[c];
            double nn = Bf - np;
            double mp = (np > 0.0) ? slsig[c] / fmax(np, 1.0) : 0.0;
            double mn = (nn > 0.0) ? (ssig[c] - slsig[c]) / fmax(nn, 1.0) : 0.0;
            double pen = 1.0 - mp + mn;
            sum_term += pen;
            if (c == 14) pen14 = pen;
        }
        // sum softplus(sig) = N*ln2 + 0.5*sum(sig) + sum(w*p)
        double sp_total = N * LN2 + 0.5 * sum_sig_all + sswp;
        double cel = (sp_total - sum_lsig_all) / N;
        out[0] = (float)(cel + 0.1 * (sum_term / 15.0));
        out[1] = (float)(0.1 * pen14);

        g_count = 0;   // reset for next (graph-replayed) launch
    }
}

extern "C" void kernel_launch(void* const* d_in, const int* in_sizes, int n_in,
                              void* d_out, int out_size)
{
    const float* outp = (const float*)d_in[0];
    const float* labp = (const float*)d_in[1];
    int n = in_sizes[0];   // 31457280 = 8192 * 3840 (exact tiles)

    static bool attr_set = false;   // attribute set is idempotent; not a stream op
    if (!attr_set) {
        cudaFuncSetAttribute(mauc_tma, cudaFuncAttributeMaxDynamicSharedMemorySize,
                             SMEM_DYN);
        attr_set = true;
    }

    mauc_tma<<<NBLK, NTHR, SMEM_DYN>>>(outp, labp, (float*)d_out, n);
}